// round 14
// baseline (speedup 1.0000x reference)
#include <cuda_runtime.h>
#include <cstdint>

// Problem constants
#define SIN   512          // input H=W
#define HW    128          // resized H=W and volume H=W
#define ND    128          // depth bins
#define NB    8            // batch
#define WIN   64           // acc depth-window rows (single pass iff span<=55)

// Scratch: per-pixel {xray_resized, (float)d_idx}
__device__ float2 g_pix[NB * HW * HW];

// ---------------------------------------------------------------------------
// Kernel A: jax.image.resize(bilinear, antialias) 512->128 for both arrays,
// fused with d_idx computation.  (R1 version, verbatim)
// ---------------------------------------------------------------------------
__global__ __launch_bounds__(128) void resize_kernel(
    const float* __restrict__ depth, const float* __restrict__ xray)
{
    __shared__ float2 hrow[SIN];   // H-contracted row at this output row: {d, x}

    const int ho  = blockIdx.x;    // 0..127
    const int b   = blockIdx.y;    // 0..7
    const int tid = threadIdx.x;   // 128 threads

    const float BW[8] = {0.125f, 0.375f, 0.625f, 0.875f,
                         0.875f, 0.625f, 0.375f, 0.125f};

    const int ih0 = 4 * ho - 2;

    float whn[8]; float hs = 0.f;
    #pragma unroll
    for (int k = 0; k < 8; k++) {
        int ih = ih0 + k;
        float w = (ih >= 0 && ih < SIN) ? BW[k] : 0.f;
        whn[k] = w; hs += w;
    }
    #pragma unroll
    for (int k = 0; k < 8; k++) whn[k] = __fdiv_rn(whn[k], hs);

    const float* dbase = depth + (size_t)b * SIN * SIN;
    const float* xbase = xray  + (size_t)b * SIN * SIN;

    {
        const int c0 = tid * 4;
        float4 ad = make_float4(0.f, 0.f, 0.f, 0.f);
        float4 ax = make_float4(0.f, 0.f, 0.f, 0.f);
        #pragma unroll
        for (int kh = 0; kh < 8; kh++) {
            if (whn[kh] != 0.f) {
                const int ih = ih0 + kh;
                const float4 dv = *(const float4*)(dbase + (size_t)ih * SIN + c0);
                const float4 xv = *(const float4*)(xbase + (size_t)ih * SIN + c0);
                const float w = whn[kh];
                ad.x = fmaf(w, dv.x, ad.x); ad.y = fmaf(w, dv.y, ad.y);
                ad.z = fmaf(w, dv.z, ad.z); ad.w = fmaf(w, dv.w, ad.w);
                ax.x = fmaf(w, xv.x, ax.x); ax.y = fmaf(w, xv.y, ax.y);
                ax.z = fmaf(w, xv.z, ax.z); ax.w = fmaf(w, xv.w, ax.w);
            }
        }
        hrow[c0 + 0] = make_float2(ad.x, ax.x);
        hrow[c0 + 1] = make_float2(ad.y, ax.y);
        hrow[c0 + 2] = make_float2(ad.z, ax.z);
        hrow[c0 + 3] = make_float2(ad.w, ax.w);
    }
    __syncthreads();

    const int wo  = tid;
    const int iw0 = 4 * wo - 2;

    float wwn[8]; float ws = 0.f;
    #pragma unroll
    for (int k = 0; k < 8; k++) {
        int iw = iw0 + k;
        float w = (iw >= 0 && iw < SIN) ? BW[k] : 0.f;
        wwn[k] = w; ws += w;
    }
    #pragma unroll
    for (int k = 0; k < 8; k++) wwn[k] = __fdiv_rn(wwn[k], ws);

    float ad = 0.f, ax = 0.f;
    #pragma unroll
    for (int k = 0; k < 8; k++) {
        if (wwn[k] != 0.f) {
            float2 p = hrow[iw0 + k];
            ad = fmaf(wwn[k], p.x, ad);
            ax = fmaf(wwn[k], p.y, ax);
        }
    }

    // d_idx = clip(int32((d/100)*127), 0, 127) — IEEE ops to match reference
    float nd = __fdiv_rn(ad, 100.0f);
    int di = (int)__fmul_rn(nd, 127.0f);
    di = min(max(di, 0), ND - 1);

    g_pix[((size_t)b * HW + ho) * HW + wo] = make_float2(ax, (float)di);
}

// ---------------------------------------------------------------------------
// Kernel B (R14): windowed accumulator (32KB smem), range-adaptive zero +
// writeout, and DEPTH-INTERLEAVED writeout: warp w owns depths d == w (mod 8)
// so the ~20 live depths spread evenly across all 8 warps (R13 concentrated
// them in 2 warps -> load imbalance was the bottleneck).
//   acc row = d - base, base = smin-4 (fast path, span<=55).
//   Taps at depths outside the live band land in rows never read back
//   == reference valid-mask drop.
// ---------------------------------------------------------------------------
__global__ __launch_bounds__(256, 6) void splat_pool_kernel(float* __restrict__ out)
{
    __shared__ float  acc[WIN * 128];   // 32KB
    __shared__ float2 pix[180];         // halo {x, d_idx}
    __shared__ int    srange[2];        // [0]=min di, [1]=max di

    const int tid = threadIdx.x;        // 0..255
    const int w0  = blockIdx.x * 16;
    const int h0  = blockIdx.y * 8;
    const int b   = blockIdx.z;

    const float inv27 = 1.0f / 27.0f;
    const float W0 = 0.13533528323661270f * inv27;  // exp(-2)/27
    const float W1 = 0.60653065971263342f * inv27;  // exp(-0.5)/27
    const float W2 = inv27;                         // exp(0)/27
    const float4 z4 = make_float4(0.f, 0.f, 0.f, 0.f);

    // Splat mapping
    const int p  = tid >> 7;        // depth parity this thread owns
    const int ct = tid & 127;       // column within 8x16 tile
    const int ty = ct >> 4;         // 0..7
    const int tx = ct & 15;         // 0..15
    // Writeout mapping (depth-interleaved across warps)
    const int g     = tid & 31;     // column group (4 cols)
    const int dwarp = tid >> 5;     // warp owns d == dwarp (mod 8)
    const int oy    = (g * 4) >> 4; // 0..7
    const int ox    = (g * 4) & 15; // 0,4,8,12
    const size_t obase = (((size_t)b * ND) * HW + (h0 + oy)) * HW + w0 + ox;

    // Phase A: stage halo pixels; init range.
    float2 q = make_float2(0.f, 64.f);
    bool valid = false;
    if (tid < 180) {
        const int ph = h0 + tid / 18 - 1;
        const int pw = w0 + tid % 18 - 1;
        if (ph >= 0 && ph < HW && pw >= 0 && pw < HW) {
            q = g_pix[((size_t)b * HW + ph) * HW + pw];
            valid = true;
        }
        pix[tid] = q;
    }
    if (tid == 0) { srange[0] = ND - 1; srange[1] = 0; }
    __syncthreads();

    // Phase B: min/max over valid halo d_idx.
    if (valid) {
        const int di = (int)q.y;
        atomicMin(&srange[0], di);
        atomicMax(&srange[1], di);
    }
    __syncthreads();

    const int smin = srange[0], smax = srange[1];
    const int span = smax - smin;
    const int olo  = max(0, smin - 3);
    const int ohi  = min(ND - 1, smax + 3);

    // Preload 9 neighbors; clamp ds into [smin-2, smax-2] (identity for valid
    // pixels; invalid ones have x=0, clamp only makes the address safe).
    float xn[9]; int dsn[9];
    #pragma unroll
    for (int dh = 0; dh < 3; dh++)
        #pragma unroll
        for (int dw = 0; dw < 3; dw++) {
            const float2 qq = pix[(ty + dh) * 18 + (tx + dw)];
            xn[dh * 3 + dw]  = qq.x;
            int ds = (int)qq.y - 2;
            dsn[dh * 3 + dw] = min(max(ds, smin - 2), smax - 2);
        }

    if (span <= 55) {
        // ================= single-pass fast path =================
        const int base = smin - 4;              // acc row = d - base

        // Zero only rows for depths [smin-4, smax+4] (clipped to [0,127]).
        {
            const int zlo = max(0, smin - 4);
            const int zhi = min(ND - 1, smax + 4);
            const int nz  = (zhi - zlo + 1) * 32;
            float4* a4 = (float4*)(acc + (zlo - base) * 128);
            for (int i = tid; i < nz; i += 256) a4[i] = z4;
        }
        __syncthreads();

        // Splat: unconditional stores, parity split (no races). Taps land in
        // rows [2, span+6]; rows outside the zeroed band are never read.
        #pragma unroll
        for (int n = 0; n < 9; n++) {
            const int   ds = dsn[n];
            const float x  = xn[n];
            const int   ks = (p - ds) & 1;      // first tap of my parity
            const float wa = ks ? W1 : W0;      // Wt[ks]
            const float wb = ks ? W1 : W2;      // Wt[ks+2]
            float* bp = &acc[(ds - base + ks) * 128 + ct];
            const float a0 = bp[0];
            const float a1 = bp[256];
            bp[0]   = fmaf(x, wa, a0);
            bp[256] = fmaf(x, wb, a1);
            if (ks == 0) {
                const float a2 = bp[512];
                bp[512] = fmaf(x, W0, a2);      // Wt[4]
            }
        }
        __syncthreads();

        // Writeout: depth-interleaved (d == dwarp mod 8), warp-uniform
        // live test; live outputs do 3 predicated LDS.128, dead are STG-zero.
        {
            const float4* a4 = (const float4*)acc;     // [64 rows][32 groups]
            #pragma unroll
            for (int i = 0; i < 16; i++) {
                const int d = dwarp + 8 * i;
                float4 o = z4;
                if (d >= olo && d <= ohi) {            // uniform across warp
                    float4 vm = (d > 0)      ? a4[(d - 1 - base) * 32 + g] : z4;
                    float4 v0 =                a4[(d     - base) * 32 + g];
                    float4 vp = (d < ND - 1) ? a4[(d + 1 - base) * 32 + g] : z4;
                    o.x = vm.x + v0.x + vp.x;
                    o.y = vm.y + v0.y + vp.y;
                    o.z = vm.z + v0.z + vp.z;
                    o.w = vm.w + v0.w + vp.w;
                }
                *(float4*)&out[obase + (size_t)d * HW * HW] = o;
            }
        }
    } else {
        // ================= multi-strip fallback (rare) =================
        // Zero outputs outside [olo, ohi].
        #pragma unroll
        for (int i = 0; i < 16; i++) {
            const int d = dwarp + 8 * i;
            if (d < olo || d > ohi)
                *(float4*)&out[obase + (size_t)d * HW * HW] = z4;
        }
        const float Wt[5] = {W0, W1, W2, W1, W0};
        for (int s0 = olo; s0 <= ohi; s0 += 54) {
            const int s1    = min(ohi, s0 + 53);
            const int base2 = s0 - 2;           // rows [1,56] hold reads
            __syncthreads();
            {   // zero whole window
                float4* a4w = (float4*)acc;
                for (int i = tid; i < WIN * 32; i += 256) a4w[i] = z4;
            }
            __syncthreads();
            // predicated splat into this window
            #pragma unroll
            for (int n = 0; n < 9; n++) {
                const int   ds = dsn[n];
                const float x  = xn[n];
                const int   ks = (p - ds) & 1;
                #pragma unroll
                for (int kk = 0; kk < 3; kk++) {
                    const int k = ks + 2 * kk;
                    if (k < 5) {
                        const int row = ds + k - base2;
                        if (row >= 0 && row < WIN)
                            acc[row * 128 + ct] =
                                fmaf(x, Wt[k], acc[row * 128 + ct]);
                    }
                }
            }
            __syncthreads();
            // writeout outputs in [s0, s1]
            const float4* a4 = (const float4*)acc;
            #pragma unroll
            for (int i = 0; i < 16; i++) {
                const int d = dwarp + 8 * i;
                if (d < s0 || d > s1) continue;
                float4 vm = (d > 0)      ? a4[(d - 1 - base2) * 32 + g] : z4;
                float4 v0 =                a4[(d     - base2) * 32 + g];
                float4 vp = (d < ND - 1) ? a4[(d + 1 - base2) * 32 + g] : z4;
                float4 o;
                o.x = vm.x + v0.x + vp.x;
                o.y = vm.y + v0.y + vp.y;
                o.z = vm.z + v0.z + vp.z;
                o.w = vm.w + v0.w + vp.w;
                *(float4*)&out[obase + (size_t)d * HW * HW] = o;
            }
        }
    }
}

// ---------------------------------------------------------------------------
extern "C" void kernel_launch(void* const* d_in, const int* in_sizes, int n_in,
                              void* d_out, int out_size)
{
    const float* depth = (const float*)d_in[0];
    const float* xray  = (const float*)d_in[1];
    float* out = (float*)d_out;

    // Kernel A: resize + d_idx
    resize_kernel<<<dim3(HW, NB), 128>>>(depth, xray);

    // Kernel B: splat + 3x3x3 box average (windowed, depth-interleaved)
    splat_pool_kernel<<<dim3(HW / 16, HW / 8, NB), 256>>>(out);
}

// round 15
// speedup vs baseline: 1.1324x; 1.1324x over previous
#include <cuda_runtime.h>
#include <cstdint>

// Problem constants
#define SIN   512          // input H=W
#define HW    128          // resized H=W and volume H=W
#define ND    128          // depth bins
#define NB    8            // batch

// Scratch: per-pixel {xray_resized, (float)d_idx}
__device__ float2 g_pix[NB * HW * HW];

// ---------------------------------------------------------------------------
// Kernel A: jax.image.resize(bilinear, antialias) 512->128 for both arrays,
// fused with d_idx computation.  (R1 version, verbatim)
// ---------------------------------------------------------------------------
__global__ __launch_bounds__(128) void resize_kernel(
    const float* __restrict__ depth, const float* __restrict__ xray)
{
    __shared__ float2 hrow[SIN];   // H-contracted row at this output row: {d, x}

    const int ho  = blockIdx.x;    // 0..127
    const int b   = blockIdx.y;    // 0..7
    const int tid = threadIdx.x;   // 128 threads

    const float BW[8] = {0.125f, 0.375f, 0.625f, 0.875f,
                         0.875f, 0.625f, 0.375f, 0.125f};

    const int ih0 = 4 * ho - 2;

    float whn[8]; float hs = 0.f;
    #pragma unroll
    for (int k = 0; k < 8; k++) {
        int ih = ih0 + k;
        float w = (ih >= 0 && ih < SIN) ? BW[k] : 0.f;
        whn[k] = w; hs += w;
    }
    #pragma unroll
    for (int k = 0; k < 8; k++) whn[k] = __fdiv_rn(whn[k], hs);

    const float* dbase = depth + (size_t)b * SIN * SIN;
    const float* xbase = xray  + (size_t)b * SIN * SIN;

    {
        const int c0 = tid * 4;
        float4 ad = make_float4(0.f, 0.f, 0.f, 0.f);
        float4 ax = make_float4(0.f, 0.f, 0.f, 0.f);
        #pragma unroll
        for (int kh = 0; kh < 8; kh++) {
            if (whn[kh] != 0.f) {
                const int ih = ih0 + kh;
                const float4 dv = *(const float4*)(dbase + (size_t)ih * SIN + c0);
                const float4 xv = *(const float4*)(xbase + (size_t)ih * SIN + c0);
                const float w = whn[kh];
                ad.x = fmaf(w, dv.x, ad.x); ad.y = fmaf(w, dv.y, ad.y);
                ad.z = fmaf(w, dv.z, ad.z); ad.w = fmaf(w, dv.w, ad.w);
                ax.x = fmaf(w, xv.x, ax.x); ax.y = fmaf(w, xv.y, ax.y);
                ax.z = fmaf(w, xv.z, ax.z); ax.w = fmaf(w, xv.w, ax.w);
            }
        }
        hrow[c0 + 0] = make_float2(ad.x, ax.x);
        hrow[c0 + 1] = make_float2(ad.y, ax.y);
        hrow[c0 + 2] = make_float2(ad.z, ax.z);
        hrow[c0 + 3] = make_float2(ad.w, ax.w);
    }
    __syncthreads();

    const int wo  = tid;
    const int iw0 = 4 * wo - 2;

    float wwn[8]; float ws = 0.f;
    #pragma unroll
    for (int k = 0; k < 8; k++) {
        int iw = iw0 + k;
        float w = (iw >= 0 && iw < SIN) ? BW[k] : 0.f;
        wwn[k] = w; ws += w;
    }
    #pragma unroll
    for (int k = 0; k < 8; k++) wwn[k] = __fdiv_rn(wwn[k], ws);

    float ad = 0.f, ax = 0.f;
    #pragma unroll
    for (int k = 0; k < 8; k++) {
        if (wwn[k] != 0.f) {
            float2 p = hrow[iw0 + k];
            ad = fmaf(wwn[k], p.x, ad);
            ax = fmaf(wwn[k], p.y, ax);
        }
    }

    // d_idx = clip(int32((d/100)*127), 0, 127) — IEEE ops to match reference
    float nd = __fdiv_rn(ad, 100.0f);
    int di = (int)__fmul_rn(nd, 127.0f);
    di = min(max(di, 0), ND - 1);

    g_pix[((size_t)b * HW + ho) * HW + wo] = make_float2(ax, (float)di);
}

// ---------------------------------------------------------------------------
// Kernel B (R15): PURE GATHER — no shared accumulator, no scatter RMW.
//   out[b,d,h,w] = sum over 3x3 (h,w) nbhd of x_n * C(d - di_n)
// where C = box3(gauss5)/27, a symmetric 7-tap profile evaluated by an
// exact-at-integers cubic in a = |d - di| (masked to 0 for a > 3).
// Rows d=0 and d=127 use an alternate cubic (the box tap at d-1 / d+1 falls
// outside the volume and is dropped) — this reproduces the reference's
// valid-mask + zero-pad pooling exactly for ANY input.
// Thread = (4-column quad, d == warp mod 8); block d-range skips dead depths.
// ---------------------------------------------------------------------------
__global__ __launch_bounds__(256) void gather_pool_kernel(float* __restrict__ out)
{
    __shared__ float2 pix[180];     // 10x18 halo {x, d_idx}
    __shared__ int    srange[2];    // [0]=min di, [1]=max di

    const int tid = threadIdx.x;    // 0..255
    const int w0  = blockIdx.x * 16;
    const int h0  = blockIdx.y * 8;
    const int b   = blockIdx.z;

    // Interior cubic: C(a), a = |d-di| in {0,1,2,3}
    const float K0 = 0.081965234053f;
    const float K1 = 0.003727095920f;
    const float K2 = -0.026871825691f;
    const float K3 = 0.005693049159f;
    // Edge cubic (d==0 or d==127): one box tap dropped
    const float K0E = 0.059501135545f;
    const float K1E = 0.029874022828f;
    const float K2E = -0.036804879457f;
    const float K3E = 0.006930856629f;

    const float4 z4 = make_float4(0.f, 0.f, 0.f, 0.f);

    // Mapping: lane g -> column quad, warp -> depth phase (d == dwarp mod 8)
    const int g     = tid & 31;     // quad index 0..31
    const int dwarp = tid >> 5;     // 0..7
    const int qh    = g >> 2;       // 0..7   (h within tile)
    const int qw4   = (g & 3) * 4;  // 0,4,8,12 (first w of quad)

    // Phase A: stage halo pixels; init range.
    float2 q = make_float2(0.f, 64.f);
    bool valid = false;
    if (tid < 180) {
        const int ph = h0 + tid / 18 - 1;
        const int pw = w0 + tid % 18 - 1;
        if (ph >= 0 && ph < HW && pw >= 0 && pw < HW) {
            q = g_pix[((size_t)b * HW + ph) * HW + pw];
            valid = true;
        }
        pix[tid] = q;
    }
    if (tid == 0) { srange[0] = ND - 1; srange[1] = 0; }
    __syncthreads();

    // Phase B: min/max over valid halo d_idx.
    if (valid) {
        const int di = (int)q.y;
        atomicMin(&srange[0], di);
        atomicMax(&srange[1], di);
    }
    __syncthreads();

    const int smin = srange[0], smax = srange[1];
    const int olo  = max(0, smin - 3);
    const int ohi  = min(ND - 1, smax + 3);

    // Load the 18 neighbors (3 h-rows x 6 w-positions) for this quad.
    // pix row = qh + r (r=0..2 covers h-1..h+1), pix col = qw4 + c (c=0..5
    // covers w-1..w+4 of the quad's 4 columns).
    float nx[18], ndi[18];
    #pragma unroll
    for (int r = 0; r < 3; r++)
        #pragma unroll
        for (int c = 0; c < 6; c++) {
            const float2 qq = pix[(qh + r) * 18 + (qw4 + c)];
            nx[r * 6 + c]  = qq.x;
            ndi[r * 6 + c] = qq.y;
        }

    const size_t obase =
        (size_t)b * ND * HW * HW + (size_t)(h0 + qh) * HW + (w0 + qw4);

    #pragma unroll
    for (int i = 0; i < 16; i++) {
        const int d = dwarp + 8 * i;            // warp-uniform depth
        float4 o = z4;
        if (d >= olo && d <= ohi) {             // warp-uniform branch
            const bool edge = (d == 0) | (d == ND - 1);
            const float c3 = edge ? K3E : K3;
            const float c2 = edge ? K2E : K2;
            const float c1 = edge ? K1E : K1;
            const float c0 = edge ? K0E : K0;
            const float df = (float)d;

            float s[6];
            #pragma unroll
            for (int c = 0; c < 6; c++) {
                float acc = 0.f;
                #pragma unroll
                for (int r = 0; r < 3; r++) {
                    const int j = r * 6 + c;
                    const float a = fabsf(df - ndi[j]);
                    float p = fmaf(a, c3, c2);
                    p = fmaf(a, p, c1);
                    p = fmaf(a, p, c0);
                    p = (a < 3.5f) ? p : 0.f;
                    acc = fmaf(nx[j], p, acc);
                }
                s[c] = acc;
            }
            o.x = s[0] + s[1] + s[2];
            o.y = s[1] + s[2] + s[3];
            o.z = s[2] + s[3] + s[4];
            o.w = s[3] + s[4] + s[5];
        }
        *(float4*)&out[obase + (size_t)d * HW * HW] = o;
    }
}

// ---------------------------------------------------------------------------
extern "C" void kernel_launch(void* const* d_in, const int* in_sizes, int n_in,
                              void* d_out, int out_size)
{
    const float* depth = (const float*)d_in[0];
    const float* xray  = (const float*)d_in[1];
    float* out = (float*)d_out;

    // Kernel A: resize + d_idx
    resize_kernel<<<dim3(HW, NB), 128>>>(depth, xray);

    // Kernel B: pure-gather splat + 3x3x3 box average
    gather_pool_kernel<<<dim3(HW / 16, HW / 8, NB), 256>>>(out);
}